// round 1
// baseline (speedup 1.0000x reference)
#include <cuda_runtime.h>
#include <math.h>

// ---------------------------------------------------------------------------
// DeformationTrajectoryAttentionBlock — fp32 implementation, factorized kv2.
// B=1, F=4, H=6, D=384, G=16, S=256, N=1024, HD=64, IMG=32, MLP_HID=1536
// ---------------------------------------------------------------------------

#define SCALE 0.125f          // HD^-0.5
#define LN_EPS 1e-5f

// scratch offsets (in floats) inside one big __device__ array
#define OFF_TOK   0LL          // 1024*384
#define OFF_XN    393216LL     // 1024*384
#define OFF_QKV   786432LL     // 1024*1152  (q:0..383, k:384..767, v:768..1151)
#define OFF_VW    1966080LL    // 6*1024*768
#define OFF_QK    6684672LL    // 6*1024*1024
#define OFF_TA    12976128LL   // 1024*256*24   ta[n][s][h*4+f]
#define OFF_XD    19267584LL   // 1024*384
#define OFF_Q2    19660800LL   // 1024*384  (already * SCALE)
#define OFF_LOG   20054016LL   // 6*1024*256
#define OFF_SA    21626880LL   // 6*1024*256
#define OFF_OPART 23199744LL   // 8*1024*384
#define OFF_O     26345472LL   // 1024*384
#define OFF_H1    26738688LL   // 1024*384
#define OFF_HN    27131904LL   // 1024*384
#define OFF_MLP   27525120LL   // 1024*1536
#define OFF_H2    29097984LL   // 1024*384
#define SCRATCH_FLOATS 29491200LL

static __device__ float g_scratch[SCRATCH_FLOATS];

// ---------------------------------------------------------------------------
// 1) MaxPool2d(2) + rearrange (b f) d x y -> (n, d);  n = f*256 + gy*16 + gx
// ---------------------------------------------------------------------------
__global__ void pool_kernel(const float* __restrict__ x)
{
    float* tok = g_scratch + OFF_TOK;
    int fd = blockIdx.x;                 // f*384 + d   (1536 blocks)
    int f = fd / 384;
    const float* xp = x + (size_t)fd * 1024;
    int t = threadIdx.x;                 // 256 threads: t = gy*16+gx
    int gy = t >> 4, gx = t & 15;
    const float* p = xp + (gy * 2) * 32 + gx * 2;
    float m = fmaxf(fmaxf(p[0], p[1]), fmaxf(p[32], p[33]));
    tok[(size_t)(f * 256 + t) * 384 + (fd % 384)] = m;
}

// ---------------------------------------------------------------------------
// LayerNorm over D=384, one block per row, 384 threads
// ---------------------------------------------------------------------------
__global__ void ln_kernel(long long inOff, const float* __restrict__ g,
                          const float* __restrict__ b, long long outOff)
{
    const float* in = g_scratch + inOff;
    float* out = g_scratch + outOff;
    int n = blockIdx.x, t = threadIdx.x;
    float x = in[(size_t)n * 384 + t];
    __shared__ float red[12];
    __shared__ float mv[2];
    float s = x;
    #pragma unroll
    for (int o = 16; o; o >>= 1) s += __shfl_xor_sync(0xffffffffu, s, o);
    if ((t & 31) == 0) red[t >> 5] = s;
    __syncthreads();
    if (t == 0) { float tt = 0.f; for (int i = 0; i < 12; i++) tt += red[i]; mv[0] = tt * (1.0f / 384.0f); }
    __syncthreads();
    float mean = mv[0];
    float d = x - mean;
    s = d * d;
    #pragma unroll
    for (int o = 16; o; o >>= 1) s += __shfl_xor_sync(0xffffffffu, s, o);
    if ((t & 31) == 0) red[t >> 5] = s;
    __syncthreads();
    if (t == 0) { float tt = 0.f; for (int i = 0; i < 12; i++) tt += red[i]; mv[1] = rsqrtf(tt * (1.0f / 384.0f) + LN_EPS); }
    __syncthreads();
    out[(size_t)n * 384 + t] = d * mv[1] * g[t] + b[t];
}

// ---------------------------------------------------------------------------
// Generic tiled SGEMM: C = alpha*A@B (+bias)(gelu)(+residual)
// 64x64x16 tiles, 256 threads, 4x4 micro-tile. flags: 1=bias 2=residual
// 4=gelu 8=B-transposed (C[n][m] = sum_k A[n][k]*B[m][k]).
// A, C, R live in g_scratch (offsets); B is either a real pointer or offset.
// All M,N multiples of 64; K multiple of 16. Batched via blockIdx.z strides.
// ---------------------------------------------------------------------------
__global__ void gemm_kernel(long long aOff, const float* __restrict__ Bp, long long bOff,
                            const float* __restrict__ bias, long long rOff, long long cOff,
                            int M, int N, int K, int lda, int ldb, int ldc, int ldr,
                            long long sA, long long sB, long long sC,
                            float alpha, int flags)
{
    const float* A = g_scratch + aOff + (long long)blockIdx.z * sA;
    const float* B = (Bp ? Bp : g_scratch + bOff) + (long long)blockIdx.z * sB;
    float* C = g_scratch + cOff + (long long)blockIdx.z * sC;
    __shared__ __align__(16) float As[16][64];
    __shared__ __align__(16) float Bs[16][64];
    int bm = blockIdx.y * 64, bn = blockIdx.x * 64;
    int tid = threadIdx.x;
    int tx = tid & 15, ty = tid >> 4;
    float acc[4][4];
    #pragma unroll
    for (int i = 0; i < 4; i++)
        #pragma unroll
        for (int j = 0; j < 4; j++) acc[i][j] = 0.f;

    for (int k0 = 0; k0 < K; k0 += 16) {
        int r = tid >> 2, k4 = (tid & 3) << 2;
        float4 av = *(const float4*)(A + (long long)(bm + r) * lda + k0 + k4);
        As[k4 + 0][r] = av.x; As[k4 + 1][r] = av.y; As[k4 + 2][r] = av.z; As[k4 + 3][r] = av.w;
        if (flags & 8) {
            float4 bv = *(const float4*)(B + (long long)(bn + r) * ldb + k0 + k4);
            Bs[k4 + 0][r] = bv.x; Bs[k4 + 1][r] = bv.y; Bs[k4 + 2][r] = bv.z; Bs[k4 + 3][r] = bv.w;
        } else {
            int kk = tid >> 4, c4 = (tid & 15) << 2;
            *(float4*)&Bs[kk][c4] = *(const float4*)(B + (long long)(k0 + kk) * ldb + bn + c4);
        }
        __syncthreads();
        #pragma unroll
        for (int kk = 0; kk < 16; kk++) {
            float4 a = *(const float4*)&As[kk][ty << 2];
            float4 b = *(const float4*)&Bs[kk][tx << 2];
            acc[0][0] += a.x * b.x; acc[0][1] += a.x * b.y; acc[0][2] += a.x * b.z; acc[0][3] += a.x * b.w;
            acc[1][0] += a.y * b.x; acc[1][1] += a.y * b.y; acc[1][2] += a.y * b.z; acc[1][3] += a.y * b.w;
            acc[2][0] += a.z * b.x; acc[2][1] += a.z * b.y; acc[2][2] += a.z * b.z; acc[2][3] += a.z * b.w;
            acc[3][0] += a.w * b.x; acc[3][1] += a.w * b.y; acc[3][2] += a.w * b.z; acc[3][3] += a.w * b.w;
        }
        __syncthreads();
    }
    int row = bm + (ty << 2), col = bn + (tx << 2);
    const float* R = g_scratch + rOff;
    #pragma unroll
    for (int i = 0; i < 4; i++) {
        #pragma unroll
        for (int j = 0; j < 4; j++) {
            float v = alpha * acc[i][j];
            if (flags & 1) v += bias[col + j];
            if (flags & 4) v = 0.5f * v * (1.0f + erff(v * 0.7071067811865476f));
            if (flags & 2) v += R[(long long)(row + i) * ldr + col + j];
            C[(long long)(row + i) * ldc + col + j] = v;
        }
    }
}

// ---------------------------------------------------------------------------
// time_attn: ta[n][s][h*4+f] = softmax_f(SCALE * qk[h][n][f*256+s])
// block = h*1024+n (6144), thread = s (256)
// ---------------------------------------------------------------------------
__global__ void ta_kernel()
{
    const float* qk = g_scratch + OFF_QK;
    float* ta = g_scratch + OFF_TA;
    int b = blockIdx.x;
    int h = b >> 10, n = b & 1023;
    int s = threadIdx.x;
    const float* p = qk + ((size_t)b << 10) + s;
    float x0 = SCALE * p[0], x1 = SCALE * p[256], x2 = SCALE * p[512], x3 = SCALE * p[768];
    float m = fmaxf(fmaxf(x0, x1), fmaxf(x2, x3));
    float e0 = expf(x0 - m), e1 = expf(x1 - m), e2 = expf(x2 - m), e3 = expf(x3 - m);
    float inv = 1.0f / (e0 + e1 + e2 + e3);
    float* o = ta + ((size_t)(n * 256 + s)) * 24 + h * 4;
    o[0] = e0 * inv; o[1] = e1 * inv; o[2] = e2 * inv; o[3] = e3 * inv;
}

// ---------------------------------------------------------------------------
// x_diag[n][c] = sum_f ta[n][n%256][h*4+f] * v[f*256 + n%256][c]   (c=h*64+hd)
// ---------------------------------------------------------------------------
__global__ void xdiag_kernel()
{
    const float* ta = g_scratch + OFF_TA;
    const float* qkv = g_scratch + OFF_QKV;
    float* xd = g_scratch + OFF_XD;
    int n = blockIdx.x, c = threadIdx.x;   // 384 threads
    int h = c >> 6;
    int s = n & 255;
    const float* tp = ta + ((size_t)(n * 256 + s)) * 24 + h * 4;
    float acc = 0.f;
    #pragma unroll
    for (int f = 0; f < 4; f++)
        acc += tp[f] * qkv[(size_t)(f * 256 + s) * 1152 + 768 + c];
    xd[(size_t)n * 384 + c] = acc;
}

// ---------------------------------------------------------------------------
// Stage-2 logits: logit[h][n][s] = q2[h,n] . (sum_j ta[n,s,j] * VWk[j, fS+s, hslice])
// CTA: 16 tokens x 32 s-values. 6 warps (warp=head), lane owns 2 cols.
// ---------------------------------------------------------------------------
__global__ void __launch_bounds__(192) logits_kernel()
{
    const float* ta = g_scratch + OFF_TA;
    const float* VW = g_scratch + OFF_VW;
    const float* q2 = g_scratch + OFF_Q2;
    float* logits = g_scratch + OFF_LOG;

    int n0 = blockIdx.x * 16;
    int s0 = blockIdx.y * 32;
    int tid = threadIdx.x;
    int h = tid >> 5, l = tid & 31;
    __shared__ __align__(16) float sta[16][24];
    float2 q2r[16];
    #pragma unroll
    for (int t = 0; t < 16; t++)
        q2r[t] = *(const float2*)(q2 + (size_t)(n0 + t) * 384 + h * 64 + 2 * l);

    for (int s = s0; s < s0 + 32; s++) {
        for (int idx = tid; idx < 384; idx += 192) {
            int t = idx / 24, j = idx % 24;
            sta[t][j] = ta[(size_t)(n0 + t) * 6144 + s * 24 + j];
        }
        __syncthreads();
        float2 vw[24];
        #pragma unroll
        for (int j = 0; j < 24; j++) {
            int hp = j >> 2, f = j & 3;
            vw[j] = *(const float2*)(VW + ((size_t)hp * 1024 + f * 256 + s) * 768 + h * 64 + 2 * l);
        }
        #pragma unroll
        for (int t = 0; t < 16; t++) {
            float k0 = 0.f, k1 = 0.f;
            const float4* tp = (const float4*)sta[t];
            #pragma unroll
            for (int j4 = 0; j4 < 6; j4++) {
                float4 tv = tp[j4];
                k0 += tv.x * vw[j4 * 4 + 0].x; k1 += tv.x * vw[j4 * 4 + 0].y;
                k0 += tv.y * vw[j4 * 4 + 1].x; k1 += tv.y * vw[j4 * 4 + 1].y;
                k0 += tv.z * vw[j4 * 4 + 2].x; k1 += tv.z * vw[j4 * 4 + 2].y;
                k0 += tv.w * vw[j4 * 4 + 3].x; k1 += tv.w * vw[j4 * 4 + 3].y;
            }
            float p = q2r[t].x * k0 + q2r[t].y * k1;
            #pragma unroll
            for (int o = 16; o; o >>= 1) p += __shfl_xor_sync(0xffffffffu, p, o);
            if (l == 0) logits[((size_t)h * 1024 + n0 + t) * 256 + s] = p;
        }
        __syncthreads();
    }
}

// ---------------------------------------------------------------------------
// softmax over s (256); writes sa scratch + space_attn output if room
// ---------------------------------------------------------------------------
__global__ void softmax_kernel(float* __restrict__ out_attn, int write_out)
{
    const float* logits = g_scratch + OFF_LOG;
    float* sa = g_scratch + OFF_SA;
    int b = blockIdx.x;           // h*1024+n
    int s = threadIdx.x;          // 256
    float x = logits[((size_t)b << 8) + s];
    __shared__ float red[8];
    __shared__ float mv[2];
    float m = x;
    #pragma unroll
    for (int o = 16; o; o >>= 1) m = fmaxf(m, __shfl_xor_sync(0xffffffffu, m, o));
    if ((s & 31) == 0) red[s >> 5] = m;
    __syncthreads();
    if (s == 0) { float t = red[0]; for (int i = 1; i < 8; i++) t = fmaxf(t, red[i]); mv[0] = t; }
    __syncthreads();
    float e = expf(x - mv[0]);
    float sum = e;
    #pragma unroll
    for (int o = 16; o; o >>= 1) sum += __shfl_xor_sync(0xffffffffu, sum, o);
    if ((s & 31) == 0) red[s >> 5] = sum;
    __syncthreads();
    if (s == 0) { float t = 0.f; for (int i = 0; i < 8; i++) t += red[i]; mv[1] = 1.0f / t; }
    __syncthreads();
    float r = e * mv[1];
    sa[((size_t)b << 8) + s] = r;
    if (write_out) out_attn[((size_t)b << 8) + s] = r;
}

// ---------------------------------------------------------------------------
// o partials: opart[sc][n][hc] += sa[h,n,s] * (sum_j ta[n,s,j] * VWv[j, fS+s, hslice])
// ---------------------------------------------------------------------------
__global__ void __launch_bounds__(192) ov_kernel()
{
    const float* ta = g_scratch + OFF_TA;
    const float* VW = g_scratch + OFF_VW;
    const float* sa = g_scratch + OFF_SA;
    float* opart = g_scratch + OFF_OPART;

    int n0 = blockIdx.x * 16;
    int sc = blockIdx.y;
    int s0 = sc * 32;
    int tid = threadIdx.x;
    int h = tid >> 5, l = tid & 31;
    __shared__ __align__(16) float sta[16][24];
    __shared__ float ssa[6][16];
    float2 oacc[16];
    #pragma unroll
    for (int t = 0; t < 16; t++) { oacc[t].x = 0.f; oacc[t].y = 0.f; }

    for (int s = s0; s < s0 + 32; s++) {
        for (int idx = tid; idx < 384; idx += 192) {
            int t = idx / 24, j = idx % 24;
            sta[t][j] = ta[(size_t)(n0 + t) * 6144 + s * 24 + j];
        }
        if (tid < 96) {
            int hh = tid >> 4, t = tid & 15;
            ssa[hh][t] = sa[((size_t)hh * 1024 + n0 + t) * 256 + s];
        }
        __syncthreads();
        float2 vw[24];
        #pragma unroll
        for (int j = 0; j < 24; j++) {
            int hp = j >> 2, f = j & 3;
            vw[j] = *(const float2*)(VW + ((size_t)hp * 1024 + f * 256 + s) * 768 + 384 + h * 64 + 2 * l);
        }
        #pragma unroll
        for (int t = 0; t < 16; t++) {
            float v0 = 0.f, v1 = 0.f;
            const float4* tp = (const float4*)sta[t];
            #pragma unroll
            for (int j4 = 0; j4 < 6; j4++) {
                float4 tv = tp[j4];
                v0 += tv.x * vw[j4 * 4 + 0].x; v1 += tv.x * vw[j4 * 4 + 0].y;
                v0 += tv.y * vw[j4 * 4 + 1].x; v1 += tv.y * vw[j4 * 4 + 1].y;
                v0 += tv.z * vw[j4 * 4 + 2].x; v1 += tv.z * vw[j4 * 4 + 2].y;
                v0 += tv.w * vw[j4 * 4 + 3].x; v1 += tv.w * vw[j4 * 4 + 3].y;
            }
            float w = ssa[h][t];
            oacc[t].x += w * v0; oacc[t].y += w * v1;
        }
        __syncthreads();
    }
    #pragma unroll
    for (int t = 0; t < 16; t++)
        *(float2*)(opart + ((size_t)sc * 1024 + n0 + t) * 384 + h * 64 + 2 * l) = oacc[t];
}

__global__ void oreduce_kernel()
{
    const float* opart = g_scratch + OFF_OPART;
    float* o = g_scratch + OFF_O;
    int i = blockIdx.x * 256 + threadIdx.x;     // < 1024*384
    float s = 0.f;
    #pragma unroll
    for (int p = 0; p < 8; p++) s += opart[(size_t)p * 393216 + i];
    o[i] = s;
}

// ---------------------------------------------------------------------------
// bilinear 16->32 upsample (half-pixel centers, edge-clamped == jax resize)
// block = f*384+d; threads 256; each thread 4 output pixels
// ---------------------------------------------------------------------------
__global__ void upsample_kernel(float* __restrict__ out, int out_size)
{
    const float* h2 = g_scratch + OFF_H2;
    int fd = blockIdx.x;
    int f = fd / 384, d = fd % 384;
    __shared__ float ch[256];
    int t = threadIdx.x;
    ch[t] = h2[(size_t)(f * 256 + t) * 384 + d];
    __syncthreads();
    #pragma unroll
    for (int p = 0; p < 4; p++) {
        int o = t + p * 256;
        int oy = o >> 5, ox = o & 31;
        float fy = 0.5f * oy - 0.25f;
        int iy0 = (int)floorf(fy);
        float wy = fy - (float)iy0;
        int iy0c = max(iy0, 0), iy1c = min(iy0 + 1, 15);
        float fx = 0.5f * ox - 0.25f;
        int ix0 = (int)floorf(fx);
        float wx = fx - (float)ix0;
        int ix0c = max(ix0, 0), ix1c = min(ix0 + 1, 15);
        float v00 = ch[iy0c * 16 + ix0c], v01 = ch[iy0c * 16 + ix1c];
        float v10 = ch[iy1c * 16 + ix0c], v11 = ch[iy1c * 16 + ix1c];
        float v = (1.f - wy) * ((1.f - wx) * v00 + wx * v01)
                + wy * ((1.f - wx) * v10 + wx * v11);
        long long oi = (long long)fd * 1024 + o;
        if (oi < (long long)out_size) out[oi] = v;
    }
}

// ---------------------------------------------------------------------------
extern "C" void kernel_launch(void* const* d_in, const int* in_sizes, int n_in,
                              void* d_out, int out_size)
{
    (void)in_sizes; (void)n_in;
    const float* x      = (const float*)d_in[0];
    const float* qkv_w  = (const float*)d_in[1];
    const float* q2_w   = (const float*)d_in[2];
    const float* kv2_w  = (const float*)d_in[3];
    const float* proj_w = (const float*)d_in[4];
    const float* proj_b = (const float*)d_in[5];
    const float* ln1_g  = (const float*)d_in[6];
    const float* ln1_b  = (const float*)d_in[7];
    const float* ln2_g  = (const float*)d_in[8];
    const float* ln2_b  = (const float*)d_in[9];
    const float* fc1_w  = (const float*)d_in[10];
    const float* fc1_b  = (const float*)d_in[11];
    const float* fc2_w  = (const float*)d_in[12];
    const float* fc2_b  = (const float*)d_in[13];
    float* out = (float*)d_out;

    // 1) patch embed + LN1
    pool_kernel<<<1536, 256>>>(x);
    ln_kernel<<<1024, 384>>>(OFF_TOK, ln1_g, ln1_b, OFF_XN);

    // 2) qkv = xn @ qkv_w  (1024x1152x384)
    gemm_kernel<<<dim3(18, 16, 1), 256>>>(OFF_XN, qkv_w, 0, nullptr, 0, OFF_QKV,
                                          1024, 1152, 384, 384, 1152, 1152, 0,
                                          0, 0, 0, 1.0f, 0);

    // 3) VW[h'] = v_h' @ kv2_w[h' slice]  (6 x 1024x768x64)
    gemm_kernel<<<dim3(12, 16, 6), 256>>>(OFF_QKV + 768, kv2_w, 0, nullptr, 0, OFF_VW,
                                          1024, 768, 64, 1152, 768, 768, 0,
                                          64, 64LL * 768, 1024LL * 768, 1.0f, 0);

    // 4) qk[h] = q_h @ k_h^T  (6 x 1024x1024x64, NT)
    gemm_kernel<<<dim3(16, 16, 6), 256>>>(OFF_QKV, nullptr, OFF_QKV + 384, nullptr, 0, OFF_QK,
                                          1024, 1024, 64, 1152, 1152, 1024, 0,
                                          64, 64, 1024LL * 1024, 1.0f, 8);

    // 5) time softmax over frames + diagonal gather
    ta_kernel<<<6144, 256>>>();
    xdiag_kernel<<<1024, 384>>>();

    // 6) q2 = SCALE * x_diag @ q2_w
    gemm_kernel<<<dim3(6, 16, 1), 256>>>(OFF_XD, q2_w, 0, nullptr, 0, OFF_Q2,
                                         1024, 384, 384, 384, 384, 384, 0,
                                         0, 0, 0, SCALE, 0);

    // 7) stage-2 logits, softmax over s, o accumulation
    logits_kernel<<<dim3(64, 8), 192>>>();
    int wout = (out_size >= 3145728) ? 1 : 0;
    softmax_kernel<<<6144, 256>>>(out + 1572864, wout);
    ov_kernel<<<dim3(64, 8), 192>>>();
    oreduce_kernel<<<1536, 256>>>();

    // 8) h1 = tok + (o @ proj_w + proj_b)
    gemm_kernel<<<dim3(6, 16, 1), 256>>>(OFF_O, proj_w, 0, proj_b, OFF_TOK, OFF_H1,
                                         1024, 384, 384, 384, 384, 384, 384,
                                         0, 0, 0, 1.0f, 1 | 2);

    // 9) LN2 + MLP + residual
    ln_kernel<<<1024, 384>>>(OFF_H1, ln2_g, ln2_b, OFF_HN);
    gemm_kernel<<<dim3(24, 16, 1), 256>>>(OFF_HN, fc1_w, 0, fc1_b, 0, OFF_MLP,
                                          1024, 1536, 384, 384, 1536, 1536, 0,
                                          0, 0, 0, 1.0f, 1 | 4);
    gemm_kernel<<<dim3(6, 16, 1), 256>>>(OFF_MLP, fc2_w, 0, fc2_b, OFF_H1, OFF_H2,
                                         1024, 384, 1536, 1536, 384, 384, 384,
                                         0, 0, 0, 1.0f, 1 | 2);

    // 10) bilinear upsample to (4,384,32,32)
    upsample_kernel<<<1536, 256>>>(out, out_size);
}